// round 1
// baseline (speedup 1.0000x reference)
#include <cuda_runtime.h>
#include <cuda_bf16.h>
#include <math_constants.h>

// Problem constants
#define BB     2
#define TT     2048
#define DMODEL 1024
#define NHEADS 16
#define DHEAD  64
#define TOTALE 1024
#define E3     3072   // 3*TOTAL

// Scratch (allocation-free: __device__ globals)
__device__ float g_qkv[BB * TT * E3];      // [B,T,3*TOTAL]
__device__ float g_att[BB * TT * TOTALE];  // [B,T,TOTAL]

// ---------------------------------------------------------------------------
// SGEMM: C[M,N] = A[M,K] (row-major) * B[N,K]^T (B row-major [N,K])
// 128x128 tile, BK=16, 256 threads, 8x8 per thread.
// ---------------------------------------------------------------------------
__global__ void __launch_bounds__(256) sgemm_nt(const float* __restrict__ A,
                                                const float* __restrict__ Bm,
                                                float* __restrict__ C,
                                                int M, int N, int K) {
    __shared__ float As[16][132];
    __shared__ float Bs[16][132];

    const int tid = threadIdx.x;
    const int bm = blockIdx.y * 128;
    const int bn = blockIdx.x * 128;
    const int tx = tid & 15;
    const int ty = tid >> 4;

    const int lrow  = tid >> 2;        // 0..63
    const int lcol4 = (tid & 3) << 2;  // 0,4,8,12

    float acc[8][8];
#pragma unroll
    for (int i = 0; i < 8; ++i)
#pragma unroll
        for (int j = 0; j < 8; ++j) acc[i][j] = 0.f;

    for (int k0 = 0; k0 < K; k0 += 16) {
#pragma unroll
        for (int r = 0; r < 2; ++r) {
            int m = lrow + r * 64;
            float4 v = *(const float4*)&A[(long)(bm + m) * K + k0 + lcol4];
            As[lcol4 + 0][m] = v.x; As[lcol4 + 1][m] = v.y;
            As[lcol4 + 2][m] = v.z; As[lcol4 + 3][m] = v.w;
        }
#pragma unroll
        for (int r = 0; r < 2; ++r) {
            int n = lrow + r * 64;
            float4 v = *(const float4*)&Bm[(long)(bn + n) * K + k0 + lcol4];
            Bs[lcol4 + 0][n] = v.x; Bs[lcol4 + 1][n] = v.y;
            Bs[lcol4 + 2][n] = v.z; Bs[lcol4 + 3][n] = v.w;
        }
        __syncthreads();

#pragma unroll
        for (int k = 0; k < 16; ++k) {
            float4 a0 = *(const float4*)&As[k][ty * 4];
            float4 a1 = *(const float4*)&As[k][ty * 4 + 64];
            float4 b0 = *(const float4*)&Bs[k][tx * 4];
            float4 b1 = *(const float4*)&Bs[k][tx * 4 + 64];
            float a[8] = {a0.x, a0.y, a0.z, a0.w, a1.x, a1.y, a1.z, a1.w};
            float b[8] = {b0.x, b0.y, b0.z, b0.w, b1.x, b1.y, b1.z, b1.w};
#pragma unroll
            for (int i = 0; i < 8; ++i)
#pragma unroll
                for (int j = 0; j < 8; ++j) acc[i][j] += a[i] * b[j];
        }
        __syncthreads();
    }

#pragma unroll
    for (int i = 0; i < 8; ++i) {
        int m = bm + ((i < 4) ? (ty * 4 + i) : (64 + ty * 4 + (i - 4)));
        float4 c0 = make_float4(acc[i][0], acc[i][1], acc[i][2], acc[i][3]);
        float4 c1 = make_float4(acc[i][4], acc[i][5], acc[i][6], acc[i][7]);
        *(float4*)&C[(long)m * N + bn + tx * 4] = c0;
        *(float4*)&C[(long)m * N + bn + 64 + tx * 4] = c1;
    }
}

// ---------------------------------------------------------------------------
// Flash attention (causal), fp32. 64 queries/block, 64-key tiles, Dh=64.
// 256 threads as 16x16; each thread owns a 4(q)x4(k / d) microtile.
// Row reductions via 16-lane shuffles (half-warp groups).
// ---------------------------------------------------------------------------
#define SPAD 68  // 64 + 4 pad, keeps float4 alignment, dodges bank conflicts

__global__ void __launch_bounds__(256) attn_kernel(const float* __restrict__ qkv,
                                                   float* __restrict__ out) {
    extern __shared__ float sm[];
    float* Qs = sm;                 // [64][SPAD]
    float* Ks = Qs + 64 * SPAD;
    float* Vs = Ks + 64 * SPAD;
    float* Ps = Vs + 64 * SPAD;

    const int qt = blockIdx.x;   // 0..31
    const int h  = blockIdx.y;   // 0..15
    const int b  = blockIdx.z;   // 0..1
    const int tid = threadIdx.x;
    const int tx = tid & 15;
    const int ty = tid >> 4;
    const int t0 = qt * 64;
    const float scale = 0.125f;  // DHEAD^-0.5

    const float* qbase = qkv + (long)b * TT * E3 + h * DHEAD;
    const float* kbase = qbase + TOTALE;
    const float* vbase = qbase + 2 * TOTALE;

    // Load Q tile [64 x 64] (float4s)
#pragma unroll
    for (int i = 0; i < 4; ++i) {
        int idx = tid + i * 256;
        int r = idx >> 4, c = (idx & 15) << 2;
        *(float4*)&Qs[r * SPAD + c] = *(const float4*)&qbase[(long)(t0 + r) * E3 + c];
    }

    float mrow[4], lrow[4], oacc[4][4];
#pragma unroll
    for (int i = 0; i < 4; ++i) {
        mrow[i] = -CUDART_INF_F; lrow[i] = 0.f;
#pragma unroll
        for (int j = 0; j < 4; ++j) oacc[i][j] = 0.f;
    }

    for (int jt = 0; jt <= qt; ++jt) {
        const int k0 = jt * 64;
        __syncthreads();  // prev AV done (and Q load complete on first iter)

        // Load K,V tiles
#pragma unroll
        for (int i = 0; i < 4; ++i) {
            int idx = tid + i * 256;
            int r = idx >> 4, c = (idx & 15) << 2;
            *(float4*)&Ks[r * SPAD + c] = *(const float4*)&kbase[(long)(k0 + r) * E3 + c];
            *(float4*)&Vs[r * SPAD + c] = *(const float4*)&vbase[(long)(k0 + r) * E3 + c];
        }
        __syncthreads();

        // S = scale * Q K^T  (4x4 per thread)
        float s[4][4];
#pragma unroll
        for (int i = 0; i < 4; ++i)
#pragma unroll
            for (int j = 0; j < 4; ++j) s[i][j] = 0.f;

#pragma unroll
        for (int d = 0; d < 64; d += 4) {
            float4 a[4], bb[4];
#pragma unroll
            for (int i = 0; i < 4; ++i) a[i]  = *(const float4*)&Qs[(ty * 4 + i) * SPAD + d];
#pragma unroll
            for (int j = 0; j < 4; ++j) bb[j] = *(const float4*)&Ks[(tx * 4 + j) * SPAD + d];
#pragma unroll
            for (int i = 0; i < 4; ++i)
#pragma unroll
                for (int j = 0; j < 4; ++j)
                    s[i][j] += a[i].x * bb[j].x + a[i].y * bb[j].y
                             + a[i].z * bb[j].z + a[i].w * bb[j].w;
        }

        const bool diag = (jt == qt);
#pragma unroll
        for (int i = 0; i < 4; ++i)
#pragma unroll
            for (int j = 0; j < 4; ++j) {
                s[i][j] *= scale;
                if (diag && (tx * 4 + j > ty * 4 + i)) s[i][j] = -CUDART_INF_F;
            }

        // Online softmax: row stats over 16-lane (tx) groups
#pragma unroll
        for (int i = 0; i < 4; ++i) {
            float rm = fmaxf(fmaxf(s[i][0], s[i][1]), fmaxf(s[i][2], s[i][3]));
#pragma unroll
            for (int off = 8; off > 0; off >>= 1)
                rm = fmaxf(rm, __shfl_xor_sync(0xffffffffu, rm, off));
            float mn = fmaxf(mrow[i], rm);
            float alpha = __expf(mrow[i] - mn);
            mrow[i] = mn;
            float rs = 0.f;
#pragma unroll
            for (int j = 0; j < 4; ++j) {
                float p = __expf(s[i][j] - mn);
                Ps[(ty * 4 + i) * SPAD + tx * 4 + j] = p;
                rs += p;
            }
#pragma unroll
            for (int off = 8; off > 0; off >>= 1)
                rs += __shfl_xor_sync(0xffffffffu, rs, off);
            lrow[i] = lrow[i] * alpha + rs;
#pragma unroll
            for (int j = 0; j < 4; ++j) oacc[i][j] *= alpha;
        }
        __syncthreads();

        // O += P V   (thread cols = d dims tx*4..+3)
#pragma unroll
        for (int k = 0; k < 64; ++k) {
            float4 vv = *(const float4*)&Vs[k * SPAD + tx * 4];
            float p0 = Ps[(ty * 4 + 0) * SPAD + k];
            float p1 = Ps[(ty * 4 + 1) * SPAD + k];
            float p2 = Ps[(ty * 4 + 2) * SPAD + k];
            float p3 = Ps[(ty * 4 + 3) * SPAD + k];
            oacc[0][0] += p0 * vv.x; oacc[0][1] += p0 * vv.y; oacc[0][2] += p0 * vv.z; oacc[0][3] += p0 * vv.w;
            oacc[1][0] += p1 * vv.x; oacc[1][1] += p1 * vv.y; oacc[1][2] += p1 * vv.z; oacc[1][3] += p1 * vv.w;
            oacc[2][0] += p2 * vv.x; oacc[2][1] += p2 * vv.y; oacc[2][2] += p2 * vv.z; oacc[2][3] += p2 * vv.w;
            oacc[3][0] += p3 * vv.x; oacc[3][1] += p3 * vv.y; oacc[3][2] += p3 * vv.z; oacc[3][3] += p3 * vv.w;
        }
    }

    // Write normalized output: out[b, t, h*64 + d]
#pragma unroll
    for (int i = 0; i < 4; ++i) {
        float inv = 1.f / lrow[i];
        int t = t0 + ty * 4 + i;
        float4 o = make_float4(oacc[i][0] * inv, oacc[i][1] * inv,
                               oacc[i][2] * inv, oacc[i][3] * inv);
        *(float4*)&out[((long)b * TT + t) * TOTALE + h * DHEAD + tx * 4] = o;
    }
}

// ---------------------------------------------------------------------------
extern "C" void kernel_launch(void* const* d_in, const int* in_sizes, int n_in,
                              void* d_out, int out_size) {
    const float* x     = (const float*)d_in[0];  // [2,2048,1024]
    const float* Wqkv  = (const float*)d_in[1];  // [3072,1024]
    const float* Wout  = (const float*)d_in[2];  // [1024,1024]
    float* out = (float*)d_out;                  // [2,2048,1024]

    void *qkv_p, *att_p;
    cudaGetSymbolAddress(&qkv_p, g_qkv);
    cudaGetSymbolAddress(&att_p, g_att);
    float* qkv = (float*)qkv_p;
    float* att = (float*)att_p;

    const int M = BB * TT;  // 4096

    // 1) QKV projection: [4096,3072] = x[4096,1024] @ Wqkv^T
    sgemm_nt<<<dim3(E3 / 128, M / 128), 256>>>(x, Wqkv, qkv, M, E3, DMODEL);

    // 2) Flash attention
    const int smem = 4 * 64 * SPAD * sizeof(float);  // 69632 B
    cudaFuncSetAttribute(attn_kernel, cudaFuncAttributeMaxDynamicSharedMemorySize, smem);
    attn_kernel<<<dim3(TT / 64, NHEADS, BB), 256, smem>>>(qkv, att);

    // 3) Output projection: [4096,1024] = att[4096,1024] @ Wout^T
    sgemm_nt<<<dim3(DMODEL / 128, M / 128), 256>>>(att, Wout, out, M, DMODEL, DMODEL);
}

// round 7
// speedup vs baseline: 3.5902x; 3.5902x over previous
#include <cstdint>
#include <cuda_runtime.h>
#include <cuda_bf16.h>
#include <math_constants.h>

#define BB     2
#define TT     2048
#define DMODEL 1024
#define NHEADS 16
#define DHEAD  64
#define TOTALE 1024
#define E3     3072

__device__ float g_qkv[BB * TT * E3];
__device__ float g_att[BB * TT * TOTALE];

__device__ __forceinline__ float to_tf32(float x) {
    uint32_t r;
    asm("cvt.rna.tf32.f32 %0, %1;" : "=r"(r) : "f"(x));
    return __uint_as_float(r);
}

#define MMA_TF32(d, a, b)                                                     \
    asm volatile("mma.sync.aligned.m16n8k8.row.col.f32.tf32.tf32.f32 "        \
                 "{%0,%1,%2,%3}, {%4,%5,%6,%7}, {%8,%9}, {%0,%1,%2,%3};"      \
                 : "+f"(d[0]), "+f"(d[1]), "+f"(d[2]), "+f"(d[3])             \
                 : "r"(a[0]), "r"(a[1]), "r"(a[2]), "r"(a[3]),                \
                   "r"(b[0]), "r"(b[1]))

// ---------------------------------------------------------------------------
// tf32 GEMM: C[M,N] = A[M,K] @ B[N,K]^T  (both row-major, K contiguous)
// 128x128 tile, BK=32, 256 threads = 8 warps (2m x 4n), warp tile 64x32.
// ---------------------------------------------------------------------------
__global__ void __launch_bounds__(256) gemm_tf32(const float* __restrict__ A,
                                                 const float* __restrict__ Bm,
                                                 float* __restrict__ C,
                                                 int M, int N, int K) {
    __shared__ float As[128][36];  // pad 36: a-frag banks = 4*(lane>>2)+(lane&3), conflict-free
    __shared__ float Bs[128][36];

    const int tid = threadIdx.x;
    const int lane = tid & 31;
    const int w = tid >> 5;
    const int wm = (w >> 2) * 64;
    const int wn = (w & 3) * 32;
    const int bm = blockIdx.y * 128;
    const int bn = blockIdx.x * 128;
    const int lr = lane >> 2;
    const int lc = lane & 3;
    const int ldr = tid >> 3;
    const int ldc = (tid & 7) << 2;

    float acc[4][4][4];
#pragma unroll
    for (int i = 0; i < 4; ++i)
#pragma unroll
        for (int j = 0; j < 4; ++j)
#pragma unroll
            for (int r = 0; r < 4; ++r) acc[i][j][r] = 0.f;

    for (int k0 = 0; k0 < K; k0 += 32) {
#pragma unroll
        for (int i = 0; i < 4; ++i) {
            int r = ldr + i * 32;
            float4 va = *(const float4*)&A[(long)(bm + r) * K + k0 + ldc];
            va.x = to_tf32(va.x); va.y = to_tf32(va.y);
            va.z = to_tf32(va.z); va.w = to_tf32(va.w);
            *(float4*)&As[r][ldc] = va;
            float4 vb = *(const float4*)&Bm[(long)(bn + r) * K + k0 + ldc];
            vb.x = to_tf32(vb.x); vb.y = to_tf32(vb.y);
            vb.z = to_tf32(vb.z); vb.w = to_tf32(vb.w);
            *(float4*)&Bs[r][ldc] = vb;
        }
        __syncthreads();

#pragma unroll
        for (int ks = 0; ks < 4; ++ks) {
            const int kb = ks * 8;
            uint32_t a[4][4], b[4][2];
#pragma unroll
            for (int mt = 0; mt < 4; ++mt) {
                int rb = wm + mt * 16 + lr;
                a[mt][0] = __float_as_uint(As[rb][kb + lc]);
                a[mt][1] = __float_as_uint(As[rb + 8][kb + lc]);
                a[mt][2] = __float_as_uint(As[rb][kb + lc + 4]);
                a[mt][3] = __float_as_uint(As[rb + 8][kb + lc + 4]);
            }
#pragma unroll
            for (int nt = 0; nt < 4; ++nt) {
                int nb = wn + nt * 8 + lr;
                b[nt][0] = __float_as_uint(Bs[nb][kb + lc]);
                b[nt][1] = __float_as_uint(Bs[nb][kb + lc + 4]);
            }
#pragma unroll
            for (int mt = 0; mt < 4; ++mt)
#pragma unroll
                for (int nt = 0; nt < 4; ++nt) MMA_TF32(acc[mt][nt], a[mt], b[nt]);
        }
        __syncthreads();
    }

#pragma unroll
    for (int mt = 0; mt < 4; ++mt) {
        int r0 = bm + wm + mt * 16 + lr;
#pragma unroll
        for (int nt = 0; nt < 4; ++nt) {
            int ccol = bn + wn + nt * 8 + 2 * lc;
            *(float2*)&C[(long)r0 * N + ccol] = make_float2(acc[mt][nt][0], acc[mt][nt][1]);
            *(float2*)&C[(long)(r0 + 8) * N + ccol] = make_float2(acc[mt][nt][2], acc[mt][nt][3]);
        }
    }
}

// ---------------------------------------------------------------------------
// Flash attention (causal), tf32 tensor cores for S=QK^T and O=PV.
// Block: 128 threads = 4 warps; 64 queries/block; warp owns 16 q-rows.
// Key tiles of 64. Softmax fp32, online.
// ---------------------------------------------------------------------------
#define QS_STRIDE 68
#define VS_STRIDE 72

__global__ void __launch_bounds__(128) attn_tf32(const float* __restrict__ qkv,
                                                 float* __restrict__ out) {
    extern __shared__ float sm[];
    float* Qs = sm;                              // [64][68]
    float* Ks = Qs + 64 * QS_STRIDE;             // [64][68]
    float* Vs = Ks + 64 * QS_STRIDE;             // [64][72]
    float* Ps = Vs + 64 * VS_STRIDE;             // [64][68]

    const int qt = blockIdx.x;
    const int h  = blockIdx.y;
    const int b  = blockIdx.z;
    const int tid = threadIdx.x;
    const int lane = tid & 31;
    const int wq = tid >> 5;        // warp -> q rows [wq*16, wq*16+16)
    const int lr = lane >> 2;
    const int lc = lane & 3;
    const int t0 = qt * 64;
    const float scale = 0.125f;

    const float* qbase = qkv + (long)b * TT * E3 + h * DHEAD;
    const float* kbase = qbase + TOTALE;
    const float* vbase = qbase + 2 * TOTALE;

    // Load Q (scaled + tf32) : 64x64
#pragma unroll
    for (int i = 0; i < 8; ++i) {
        int idx = tid + i * 128;
        int r = idx >> 4, c4 = (idx & 15) << 2;
        float4 v = *(const float4*)&qbase[(long)(t0 + r) * E3 + c4];
        v.x = to_tf32(v.x * scale); v.y = to_tf32(v.y * scale);
        v.z = to_tf32(v.z * scale); v.w = to_tf32(v.w * scale);
        *(float4*)&Qs[r * QS_STRIDE + c4] = v;
    }

    float m0 = -CUDART_INF_F, m1 = -CUDART_INF_F, l0 = 0.f, l1 = 0.f;
    float o[8][4];
#pragma unroll
    for (int nt = 0; nt < 8; ++nt)
#pragma unroll
        for (int r = 0; r < 4; ++r) o[nt][r] = 0.f;

    for (int jt = 0; jt <= qt; ++jt) {
        const int k0 = jt * 64;
        __syncthreads();  // prior PV done with Ks/Vs (and Q load visible on iter 0)
#pragma unroll
        for (int i = 0; i < 8; ++i) {
            int idx = tid + i * 128;
            int r = idx >> 4, c4 = (idx & 15) << 2;
            float4 vk = *(const float4*)&kbase[(long)(k0 + r) * E3 + c4];
            vk.x = to_tf32(vk.x); vk.y = to_tf32(vk.y);
            vk.z = to_tf32(vk.z); vk.w = to_tf32(vk.w);
            *(float4*)&Ks[r * QS_STRIDE + c4] = vk;
            float4 vv = *(const float4*)&vbase[(long)(k0 + r) * E3 + c4];
            vv.x = to_tf32(vv.x); vv.y = to_tf32(vv.y);
            vv.z = to_tf32(vv.z); vv.w = to_tf32(vv.w);
            *(float4*)&Vs[r * VS_STRIDE + c4] = vv;
        }
        __syncthreads();

        // ---- S = Q K^T  (warp: 16 rows x 64 keys, 8 ntiles, 8 ksteps)
        float sacc[8][4];
#pragma unroll
        for (int nt = 0; nt < 8; ++nt)
#pragma unroll
            for (int r = 0; r < 4; ++r) sacc[nt][r] = 0.f;

#pragma unroll
        for (int ks = 0; ks < 8; ++ks) {
            const int kb = ks * 8;
            uint32_t a[4];
            int rb = wq * 16 + lr;
            a[0] = __float_as_uint(Qs[rb * QS_STRIDE + kb + lc]);
            a[1] = __float_as_uint(Qs[(rb + 8) * QS_STRIDE + kb + lc]);
            a[2] = __float_as_uint(Qs[rb * QS_STRIDE + kb + lc + 4]);
            a[3] = __float_as_uint(Qs[(rb + 8) * QS_STRIDE + kb + lc + 4]);
#pragma unroll
            for (int nt = 0; nt < 8; ++nt) {
                uint32_t bfr[2];
                int nb = nt * 8 + lr;
                bfr[0] = __float_as_uint(Ks[nb * QS_STRIDE + kb + lc]);
                bfr[1] = __float_as_uint(Ks[nb * QS_STRIDE + kb + lc + 4]);
                MMA_TF32(sacc[nt], a, bfr);
            }
        }

        // ---- causal mask (diagonal tile only; scale already folded into Q)
        if (jt == qt) {
            int row0 = wq * 16 + lr, row1 = row0 + 8;
#pragma unroll
            for (int nt = 0; nt < 8; ++nt) {
                int col = nt * 8 + 2 * lc;
                if (col > row0)     sacc[nt][0] = -CUDART_INF_F;
                if (col + 1 > row0) sacc[nt][1] = -CUDART_INF_F;
                if (col > row1)     sacc[nt][2] = -CUDART_INF_F;
                if (col + 1 > row1) sacc[nt][3] = -CUDART_INF_F;
            }
        }

        // ---- online softmax (row group = 4 consecutive lanes)
        float rm0 = -CUDART_INF_F, rm1 = -CUDART_INF_F;
#pragma unroll
        for (int nt = 0; nt < 8; ++nt) {
            rm0 = fmaxf(rm0, fmaxf(sacc[nt][0], sacc[nt][1]));
            rm1 = fmaxf(rm1, fmaxf(sacc[nt][2], sacc[nt][3]));
        }
        rm0 = fmaxf(rm0, __shfl_xor_sync(0xffffffffu, rm0, 1));
        rm0 = fmaxf(rm0, __shfl_xor_sync(0xffffffffu, rm0, 2));
        rm1 = fmaxf(rm1, __shfl_xor_sync(0xffffffffu, rm1, 1));
        rm1 = fmaxf(rm1, __shfl_xor_sync(0xffffffffu, rm1, 2));

        float mn0 = fmaxf(m0, rm0), mn1 = fmaxf(m1, rm1);
        float alpha0 = __expf(m0 - mn0), alpha1 = __expf(m1 - mn1);
        m0 = mn0; m1 = mn1;

        const int pr0 = wq * 16 + lr, pr1 = pr0 + 8;
        float rs0 = 0.f, rs1 = 0.f;
#pragma unroll
        for (int nt = 0; nt < 8; ++nt) {
            float p0 = __expf(sacc[nt][0] - mn0);
            float p1 = __expf(sacc[nt][1] - mn0);
            float p2 = __expf(sacc[nt][2] - mn1);
            float p3 = __expf(sacc[nt][3] - mn1);
            rs0 += p0 + p1; rs1 += p2 + p3;
            int cl = nt * 8 + 2 * lc;
            *(float2*)&Ps[pr0 * QS_STRIDE + cl] = make_float2(to_tf32(p0), to_tf32(p1));
            *(float2*)&Ps[pr1 * QS_STRIDE + cl] = make_float2(to_tf32(p2), to_tf32(p3));
        }
        rs0 += __shfl_xor_sync(0xffffffffu, rs0, 1);
        rs0 += __shfl_xor_sync(0xffffffffu, rs0, 2);
        rs1 += __shfl_xor_sync(0xffffffffu, rs1, 1);
        rs1 += __shfl_xor_sync(0xffffffffu, rs1, 2);
        l0 = l0 * alpha0 + rs0;
        l1 = l1 * alpha1 + rs1;
#pragma unroll
        for (int nt = 0; nt < 8; ++nt) {
            o[nt][0] *= alpha0; o[nt][1] *= alpha0;
            o[nt][2] *= alpha1; o[nt][3] *= alpha1;
        }
        __syncwarp();  // Ps rows are warp-private: order STS before LDS

        // ---- O += P V  (1 mtile x 8 ntiles x 8 ksteps)
#pragma unroll
        for (int ks = 0; ks < 8; ++ks) {
            const int kb = ks * 8;
            uint32_t a[4];
            int rb = wq * 16 + lr;
            a[0] = __float_as_uint(Ps[rb * QS_STRIDE + kb + lc]);
            a[1] = __float_as_uint(Ps[(rb + 8) * QS_STRIDE + kb + lc]);
            a[2] = __float_as_uint(Ps[rb * QS_STRIDE + kb + lc + 4]);
            a[3] = __float_as_uint(Ps[(rb + 8) * QS_STRIDE + kb + lc + 4]);
#pragma unroll
            for (int nt = 0; nt < 8; ++nt) {
                uint32_t bfr[2];
                bfr[0] = __float_as_uint(Vs[(kb + lc) * VS_STRIDE + nt * 8 + lr]);
                bfr[1] = __float_as_uint(Vs[(kb + lc + 4) * VS_STRIDE + nt * 8 + lr]);
                MMA_TF32(o[nt], a, bfr);
            }
        }
        __syncwarp();  // next iteration's Ps writes must not pass these reads
    }

    // ---- epilogue
    float inv0 = 1.f / l0, inv1 = 1.f / l1;
    int r0 = t0 + wq * 16 + lr, r1 = r0 + 8;
#pragma unroll
    for (int nt = 0; nt < 8; ++nt) {
        int d = h * DHEAD + nt * 8 + 2 * lc;
        *(float2*)&out[((long)b * TT + r0) * TOTALE + d] =
            make_float2(o[nt][0] * inv0, o[nt][1] * inv0);
        *(float2*)&out[((long)b * TT + r1) * TOTALE + d] =
            make_float2(o[nt][2] * inv1, o[nt][3] * inv1);
    }
}

// ---------------------------------------------------------------------------
extern "C" void kernel_launch(void* const* d_in, const int* in_sizes, int n_in,
                              void* d_out, int out_size) {
    const float* x    = (const float*)d_in[0];
    const float* Wqkv = (const float*)d_in[1];
    const float* Wout = (const float*)d_in[2];
    float* out = (float*)d_out;

    void *qkv_p, *att_p;
    cudaGetSymbolAddress(&qkv_p, g_qkv);
    cudaGetSymbolAddress(&att_p, g_att);
    float* qkv = (float*)qkv_p;
    float* att = (float*)att_p;

    const int M = BB * TT;

    gemm_tf32<<<dim3(E3 / 128, M / 128), 256>>>(x, Wqkv, qkv, M, E3, DMODEL);

    const int smem = (64 * QS_STRIDE * 3 + 64 * VS_STRIDE) * sizeof(float);  // 70656 B
    cudaFuncSetAttribute(attn_tf32, cudaFuncAttributeMaxDynamicSharedMemorySize, smem);
    attn_tf32<<<dim3(TT / 64, NHEADS, BB), 128, smem>>>(qkv, att);

    gemm_tf32<<<dim3(DMODEL / 128, M / 128), 256>>>(att, Wout, out, M, DMODEL, DMODEL);
}